// round 10
// baseline (speedup 1.0000x reference)
#include <cuda_runtime.h>

// Inputs (metadata order): x0 [N*D f32], x1 [N*D f32], x_c_0, x_c_1 (unused), y [N i32]
// Output: scalar f32 loss.
//
// loss = sum_i [ y_i * ||x0_i - x1_i||^2 + (1-y_i) * max(0, 1.2 - ||x0_i - x1_i||) ] / (2N)
// (everything else in the reference is dead code w.r.t. the returned value)

#define NBUCKETS 32
#define BSTRIDE  32   // 32 floats = 128 B between buckets (distinct L2 lines)

// Zero-initialized at module load (.bss); finalize_kernel re-zeroes after each
// read, so every graph replay starts from zeroed buckets. Deterministic work.
__device__ float g_bucket[NBUCKETS * BSTRIDE];

// ---------------- Kernel 1: per-row loss term -> bucketed atomic -------------
__global__ __launch_bounds__(256, 8)
void row_loss_kernel(const float4* __restrict__ x0,
                     const float4* __restrict__ x1,
                     const int* __restrict__ y,
                     int Dvec)                 // D / 4
{
    const int row  = blockIdx.x;
    const int lane = threadIdx.x & 31;
    const int wid  = threadIdx.x >> 5;

    // Hoisted broadcast label load, off the critical path.
    const float yf = (float)y[row];

    const size_t base = (size_t)row * (size_t)Dvec;
    const float4* a = x0 + base;
    const float4* b = x1 + base;

    float s = 0.0f;
    // Dvec = 1024, 256 threads -> 4 iterations; full unroll front-batches
    // 8 independent LDG.128 per thread. Default cache policy (R1-measured best).
    #pragma unroll 4
    for (int i = threadIdx.x; i < Dvec; i += 256) {
        float4 av = a[i];
        float4 bv = b[i];
        float dx = av.x - bv.x;
        float dy = av.y - bv.y;
        float dz = av.z - bv.z;
        float dw = av.w - bv.w;
        s = fmaf(dx, dx, s);
        s = fmaf(dy, dy, s);
        s = fmaf(dz, dz, s);
        s = fmaf(dw, dw, s);
    }

    // Warp reduce
    #pragma unroll
    for (int o = 16; o > 0; o >>= 1)
        s += __shfl_xor_sync(0xffffffffu, s, o);

    __shared__ float wsum[8];
    if (lane == 0) wsum[wid] = s;
    __syncthreads();

    if (wid == 0) {
        s = (lane < 8) ? wsum[lane] : 0.0f;
        #pragma unroll
        for (int o = 4; o > 0; o >>= 1)
            s += __shfl_xor_sync(0xffffffffu, s, o);
        if (lane == 0) {
            const float e_dist    = sqrtf(s);
            const float e_clamped = fmaxf(1.2f - e_dist, 0.0f);
            const float term = yf * s + (1.0f - yf) * e_clamped;
            // 4096 atomics spread over 32 distinct 128B-separated addresses:
            // ~128 ops/address at L2, fully hidden under the memory stream.
            atomicAdd(&g_bucket[(row & (NBUCKETS - 1)) * BSTRIDE], term);
        }
    }
}

// ---------------- Kernel 2: single-warp finalize ------------------------------
// 32 lanes read 32 buckets (one L2 round trip), reduce, store scalar, and
// re-zero the buckets for the next graph replay.
__global__ __launch_bounds__(32, 1)
void finalize_kernel(float* __restrict__ out, float inv_2N)
{
    const int lane = threadIdx.x;

    float t = g_bucket[lane * BSTRIDE];

    #pragma unroll
    for (int o = 16; o > 0; o >>= 1)
        t += __shfl_xor_sync(0xffffffffu, t, o);

    if (lane == 0)
        out[0] = t * inv_2N;

    // Reset for next replay (all lanes, after the value is consumed).
    g_bucket[lane * BSTRIDE] = 0.0f;
}

extern "C" void kernel_launch(void* const* d_in, const int* in_sizes, int n_in,
                              void* d_out, int out_size) {
    const float* x0 = (const float*)d_in[0];
    const float* x1 = (const float*)d_in[1];
    const int*   y  = (const int*)d_in[4];
    float* out = (float*)d_out;

    const int N = in_sizes[4];          // 4096
    const int D = in_sizes[0] / N;      // 4096
    const int Dvec = D / 4;             // 1024
    const float inv_2N = 0.5f / (float)N;

    row_loss_kernel<<<N, 256>>>((const float4*)x0, (const float4*)x1, y, Dvec);
    finalize_kernel<<<1, 32>>>(out, inv_2N);
}